// round 9
// baseline (speedup 1.0000x reference)
#include <cuda_runtime.h>
#include <cstdint>

// Fixed shapes from reference setup_inputs
#define BS   32
#define C    256
#define HW   4096          // 64*64
#define HID  32            // C / R
#define NPLANES (BS * C)   // 8192

#define NCHUNK   2
#define B_PER_CH (BS / NCHUNK)              // 16 batches
#define P_PER_CH (B_PER_CH * C)             // 4096 planes = 67MB < 126MB L2

// Scratch in device globals (no allocations allowed)
__device__ float  g_pooled[NPLANES];   // [BS, C] plane means
__device__ float4 g_coef[NPLANES];     // (a0, a1, q0, q1) per (b,c)

// ---------------------------------------------------------------------------
// Kernel 1: mean pool for one chunk. One CTA per plane, 256 threads, 4
// front-batched float4 loads. Default .ca reads: the whole 67MB chunk is
// L2-resident when this kernel finishes.
// ---------------------------------------------------------------------------
__global__ __launch_bounds__(256) void pool_kernel(const float* __restrict__ x,
                                                   int pbase) {
    const int p = pbase + blockIdx.x;
    const int t = threadIdx.x;
    const float4* __restrict__ x4 = reinterpret_cast<const float4*>(x) + (size_t)p * (HW / 4);

    float4 v0 = x4[t];
    float4 v1 = x4[t + 256];
    float4 v2 = x4[t + 512];
    float4 v3 = x4[t + 768];

    float s = ((v0.x + v0.y) + (v0.z + v0.w))
            + ((v1.x + v1.y) + (v1.z + v1.w))
            + ((v2.x + v2.y) + (v2.z + v2.w))
            + ((v3.x + v3.y) + (v3.z + v3.w));

#pragma unroll
    for (int o = 16; o > 0; o >>= 1) s += __shfl_down_sync(0xffffffffu, s, o);

    __shared__ float ws[8];
    if ((t & 31) == 0) ws[t >> 5] = s;
    __syncthreads();
    if (t < 8) {
        float v = ws[t];
#pragma unroll
        for (int o = 4; o > 0; o >>= 1) v += __shfl_down_sync(0xffu, v, o);
        if (t == 0) g_pooled[p] = v * (1.0f / (float)HW);
    }
}

// ---------------------------------------------------------------------------
// Kernel 2: coefficients for one chunk. One CTA per batch element.
// ---------------------------------------------------------------------------
__global__ __launch_bounds__(256) void coef_kernel(const float* __restrict__ w1,
                                                   const float* __restrict__ b1,
                                                   const float* __restrict__ w2,
                                                   const float* __restrict__ b2,
                                                   int bbase) {
    const int b = bbase + blockIdx.x;
    const int t = threadIdx.x;

    __shared__ float sp[C];
    __shared__ float sh[HID];

    sp[t] = g_pooled[b * C + t];
    __syncthreads();

    if (t < HID) {
        float acc = b1[t];
        const float* __restrict__ w1r = w1 + t * C;
#pragma unroll 8
        for (int i = 0; i < C; ++i) acc = fmaf(sp[i], w1r[i], acc);
        sh[t] = fmaxf(acc, 0.f);
    }
    __syncthreads();

    const int cc = t;
    float z00 = b2[2 * cc];               // k=0 alpha
    float z01 = b2[2 * cc + 1];           // k=0 beta
    float z10 = b2[512 + 2 * cc];         // k=1 alpha
    float z11 = b2[512 + 2 * cc + 1];     // k=1 beta
    const float* __restrict__ r00 = w2 + (size_t)(2 * cc) * HID;
    const float* __restrict__ r01 = w2 + (size_t)(2 * cc + 1) * HID;
    const float* __restrict__ r10 = w2 + (size_t)(512 + 2 * cc) * HID;
    const float* __restrict__ r11 = w2 + (size_t)(512 + 2 * cc + 1) * HID;
#pragma unroll
    for (int h = 0; h < HID; ++h) {
        const float hv = sh[h];
        z00 = fmaf(hv, r00[h], z00);
        z01 = fmaf(hv, r01[h], z01);
        z10 = fmaf(hv, r10[h], z10);
        z11 = fmaf(hv, r11[h], z11);
    }
    float4 cf;
    cf.x = 1.0f + tanhf(0.5f * z00);          // a0 = 1 + 1.0*delta
    cf.y =        tanhf(0.5f * z10);          // a1 = 0 + 1.0*delta
    cf.z = 1.0f + 0.5f * tanhf(0.5f * z01);   // q0 = 1 + 0.5*delta
    cf.w =        0.5f * tanhf(0.5f * z11);   // q1 = 0 + 0.5*delta
    g_coef[b * C + cc] = cf;
}

// ---------------------------------------------------------------------------
// Kernel 3: apply for one chunk: out = max(x*a0+q0, x*a1+q1).
// Two planes per CTA, 8 front-batched float4 loads (MLP=8). The chunk's x is
// L2-resident from the pool pass: __ldcs reads hit and demote; __stcs writes
// are evict-first so the out stream doesn't displace the x chunk.
// ---------------------------------------------------------------------------
__global__ __launch_bounds__(256) void apply_kernel(const float* __restrict__ x,
                                                    float* __restrict__ out,
                                                    int pbase) {
    const int p0 = pbase + 2 * blockIdx.x;
    const int p1 = p0 + 1;
    const int t  = threadIdx.x;

    const float4 cf0 = __ldcg(&g_coef[p0]);
    const float4 cf1 = __ldcg(&g_coef[p1]);

    const float4* __restrict__ xa = reinterpret_cast<const float4*>(x) + (size_t)p0 * (HW / 4);
    const float4* __restrict__ xb = reinterpret_cast<const float4*>(x) + (size_t)p1 * (HW / 4);
    float4* __restrict__ oa = reinterpret_cast<float4*>(out) + (size_t)p0 * (HW / 4);
    float4* __restrict__ ob = reinterpret_cast<float4*>(out) + (size_t)p1 * (HW / 4);

    float4 a0v = __ldcs(&xa[t]);
    float4 a1v = __ldcs(&xa[t + 256]);
    float4 a2v = __ldcs(&xa[t + 512]);
    float4 a3v = __ldcs(&xa[t + 768]);
    float4 b0v = __ldcs(&xb[t]);
    float4 b1v = __ldcs(&xb[t + 256]);
    float4 b2v = __ldcs(&xb[t + 512]);
    float4 b3v = __ldcs(&xb[t + 768]);

#define APPLY4(r, v, cf)                                                     \
    r.x = fmaxf(fmaf(v.x, cf.x, cf.z), fmaf(v.x, cf.y, cf.w));               \
    r.y = fmaxf(fmaf(v.y, cf.x, cf.z), fmaf(v.y, cf.y, cf.w));               \
    r.z = fmaxf(fmaf(v.z, cf.x, cf.z), fmaf(v.z, cf.y, cf.w));               \
    r.w = fmaxf(fmaf(v.w, cf.x, cf.z), fmaf(v.w, cf.y, cf.w));

    float4 r;
    APPLY4(r, a0v, cf0) __stcs(&oa[t],       r);
    APPLY4(r, a1v, cf0) __stcs(&oa[t + 256], r);
    APPLY4(r, a2v, cf0) __stcs(&oa[t + 512], r);
    APPLY4(r, a3v, cf0) __stcs(&oa[t + 768], r);
    APPLY4(r, b0v, cf1) __stcs(&ob[t],       r);
    APPLY4(r, b1v, cf1) __stcs(&ob[t + 256], r);
    APPLY4(r, b2v, cf1) __stcs(&ob[t + 512], r);
    APPLY4(r, b3v, cf1) __stcs(&ob[t + 768], r);
#undef APPLY4
}

extern "C" void kernel_launch(void* const* d_in, const int* in_sizes, int n_in,
                              void* d_out, int out_size) {
    const float* x  = (const float*)d_in[0];
    const float* w1 = (const float*)d_in[1];
    const float* b1 = (const float*)d_in[2];
    const float* w2 = (const float*)d_in[3];
    const float* b2 = (const float*)d_in[4];
    float* out = (float*)d_out;

    for (int c = 0; c < NCHUNK; ++c) {
        const int pbase = c * P_PER_CH;
        const int bbase = c * B_PER_CH;
        pool_kernel <<<P_PER_CH,     256>>>(x, pbase);
        coef_kernel <<<B_PER_CH,     256>>>(w1, b1, w2, b2, bbase);
        apply_kernel<<<P_PER_CH / 2, 256>>>(x, out, pbase);
    }
}